// round 11
// baseline (speedup 1.0000x reference)
#include <cuda_runtime.h>
#include <cuda_fp16.h>
#include <cstdint>

#define BB 16
#define NN 16384
#define CC 128
#define KK 9
#define TM 128
#define THREADS 512
#define NCHUNK_CONV 72          // 8 c8-slices * 9 ko, K=16 each
#define NCHUNK 80               // + 8 skip chunks
#define CHUNK_GB 4096
#define ROW_SB 48               // smem row stride: 32B data + 16B pad
#define BUF_B (128 * ROW_SB)    // 6144
#define NWBUF 4

// smem layout (bytes)
#define WBUF_OFF 0                          // 4 * 6144
#define ABUF_OFF (NWBUF * BUF_B)            // 24576 (+2*6144)
#define P2_OFF   (ABUF_OFF + 2 * BUF_B)     // 36864
#define IDX_OFF  (P2_OFF + 128 * 108 * 4)   // 92160
#define BIAS_OFF (IDX_OFF + 128 * KK * 4)   // 96768
#define SMEM_TOTAL (BIAS_OFF + 1024)        // 97792

__device__ __align__(16) __half g_Wc[NCHUNK_CONV * 2048];
__device__ __align__(16) __half g_Ws[8 * 2048];

__host__ __device__ __forceinline__ int perm16(int p) {
    int e = p & 1;
    return (p < 8) ? ((p >> 1) * 4 + e) : (((p - 8) >> 1) * 4 + 2 + e);
}

__global__ void prep_w(const float* __restrict__ Wc, const float* __restrict__ Ws) {
    int t = blockIdx.x * blockDim.x + threadIdx.x;
    if (t < NCHUNK_CONV * 2048) {
        int qn = t >> 11, r = t & 2047, o = r >> 4, p = r & 15;
        int c8 = qn / 9, ko = qn % 9;
        g_Wc[t] = __float2half_rn(Wc[o * 1152 + ko * CC + c8 * 16 + perm16(p)]);
    }
    if (t < 8 * 2048) {
        int qn = t >> 11, r = t & 2047, o = r >> 4, p = r & 15;
        g_Ws[t] = __float2half_rn(Ws[o * CC + qn * 16 + perm16(p)]);
    }
}

// ---------------- PTX helpers ----------------
__device__ __forceinline__ uint32_t smem_u32(const void* p) {
    uint32_t a;
    asm("{ .reg .u64 t; cvta.to.shared.u64 t, %1; cvt.u32.u64 %0, t; }" : "=r"(a) : "l"(p));
    return a;
}
#define CP_ASYNC16(dst, src) \
    asm volatile("cp.async.cg.shared.global [%0], [%1], 16;" :: "r"(dst), "l"(src))
#define CP_COMMIT() asm volatile("cp.async.commit_group;" ::: "memory")
#define CP_WAIT(n)  asm volatile("cp.async.wait_group %0;" :: "n"(n) : "memory")

__device__ __forceinline__ void ldsm_x4(uint32_t* r, uint32_t addr) {
    asm volatile("ldmatrix.sync.aligned.m8n8.x4.shared.b16 {%0,%1,%2,%3}, [%4];"
                 : "=r"(r[0]), "=r"(r[1]), "=r"(r[2]), "=r"(r[3]) : "r"(addr));
}
__device__ __forceinline__ void mma16816(float* c, const uint32_t* a,
                                         uint32_t b0, uint32_t b1) {
    asm volatile("mma.sync.aligned.m16n8k16.row.col.f32.f16.f16.f32 "
                 "{%0,%1,%2,%3}, {%4,%5,%6,%7}, {%8,%9}, {%0,%1,%2,%3};"
                 : "+f"(c[0]), "+f"(c[1]), "+f"(c[2]), "+f"(c[3])
                 : "r"(a[0]), "r"(a[1]), "r"(a[2]), "r"(a[3]), "r"(b0), "r"(b1));
}
__device__ __forceinline__ float elu(float v) {
    float e;
    asm("ex2.approx.f32 %0, %1;" : "=f"(e) : "f"(v * 1.44269504f));
    return v > 0.f ? v : e - 1.f;
}
__device__ __forceinline__ void fma4(float4& a, float s, const float4& v) {
    a.x = fmaf(s, v.x, a.x); a.y = fmaf(s, v.y, a.y);
    a.z = fmaf(s, v.z, a.z); a.w = fmaf(s, v.w, a.w);
}
__device__ __forceinline__ uint32_t h2pack(float a, float b) {
    __half2 h = __floats2half2_rn(a, b);
    return *reinterpret_cast<uint32_t*>(&h);
}

// chunk fetch: threads 0..255 push 16B each (4KB chunk); everyone commits
__device__ __forceinline__ void issue_chunk(uint32_t wbase, int i, int tid) {
    if (tid < 256) {
        const char* src = (i < NCHUNK_CONV)
            ? (const char*)g_Wc + (size_t)i * CHUNK_GB
            : (const char*)g_Ws + (size_t)(i - NCHUNK_CONV) * CHUNK_GB;
        int o = tid >> 1, h = tid & 1;
        uint32_t dst = wbase + (i & (NWBUF - 1)) * BUF_B + o * ROW_SB + h * 16;
        CP_ASYNC16(dst, src + o * 32 + h * 16);
    }
    CP_COMMIT();
}

__global__ __launch_bounds__(THREADS, 1)
void paiconv_pl(const float* __restrict__ x, const int* __restrict__ idxg,
                const float* __restrict__ P, const float* __restrict__ b_conv,
                const float* __restrict__ b_skip, float* __restrict__ out)
{
    extern __shared__ char smem[];
    const uint32_t sb = smem_u32(smem);
    const int tid  = threadIdx.x;
    const int lane = tid & 31;
    const int wid  = tid >> 5;
    const int n0   = blockIdx.x * TM;
    const int b    = blockIdx.y;

    float* s_P2   = (float*)(smem + P2_OFF);     // [node][ko][12]
    int*   s_idx  = (int*)(smem + IDX_OFF);
    float* s_bias = (float*)(smem + BIAS_OFF);

    issue_chunk(sb + WBUF_OFF, 0, tid);
    issue_chunk(sb + WBUF_OFF, 1, tid);
    issue_chunk(sb + WBUF_OFF, 2, tid);

    for (int t = tid; t < TM * 81; t += THREADS) {
        int node = t / 81, rem = t - node * 81;
        int ko = rem / 9, j = rem - ko * 9;
        s_P2[node * 108 + ko * 12 + j] = P[(size_t)n0 * 81 + t];
    }
    for (int t = tid; t < TM * KK; t += THREADS) s_idx[t] = idxg[n0 * KK + t];
    if (tid < CC)       s_bias[tid] = b_conv[tid];
    else if (tid < 256) s_bias[tid] = b_skip[tid - CC];
    __syncthreads();

    const float* xb = x + (size_t)b * NN * CC;

    // mix role: thread owns (node row, 4-channel group)
    const int row = tid >> 2;
    const int q4  = (tid & 3) * 16;
    const uint32_t a_st = sb + ABUF_OFF + row * ROW_SB + (tid & 3) * 4;

    // MMA role: 16 warps, 4m x 4n grid, tile m32 x n32
    const int mrow = (wid >> 2) * 32;
    const int ncol = (wid & 3) * 32;
    const uint32_t a_l0 = sb + ABUF_OFF + (mrow + (lane & 15)) * ROW_SB + (lane >> 4) * 16;
    const uint32_t b_l0 = sb + WBUF_OFF + (ncol + (lane & 15)) * ROW_SB + (lane >> 4) * 16;

    uint32_t noff[KK];
    #pragma unroll
    for (int j = 0; j < KK; j++) {
        unsigned ix = (unsigned)s_idx[row * KK + j];
        noff[j] = (ix < (unsigned)NN) ? ix * 512u : 0xFFFFFFFFu;
    }

    // acc layout: group g in [0,8): acc[g*4 .. g*4+3] = (m-half g>>2, n-octet g&3)
    float acc[32];
    #pragma unroll
    for (int i = 0; i < 32; i++) acc[i] = 0.f;

    float4 xg[KK];

    // ---- prologue: gather c8=0, mix chunk 0 -> A[0] ----
    #pragma unroll
    for (int j = 0; j < KK; j++) {
        float4 v = make_float4(0.f, 0.f, 0.f, 0.f);
        if (noff[j] != 0xFFFFFFFFu)
            v = __ldg((const float4*)((const char*)xb + (size_t)noff[j] + q4));
        xg[j] = v;
    }
    {
        const float* p = s_P2 + row * 108;       // ko = 0
        float4 pa = *(const float4*)p, pb = *(const float4*)(p + 4);
        float4 v = make_float4(0.f, 0.f, 0.f, 0.f);
        fma4(v, pa.x, xg[0]); fma4(v, pa.y, xg[1]);
        fma4(v, pa.z, xg[2]); fma4(v, pa.w, xg[3]);
        fma4(v, pb.x, xg[4]); fma4(v, pb.y, xg[5]);
        fma4(v, pb.z, xg[6]); fma4(v, pb.w, xg[7]);
        fma4(v, p[8], xg[8]);
        uint32_t h0 = h2pack(elu(v.x), elu(v.y));
        uint32_t h1 = h2pack(elu(v.z), elu(v.w));
        asm volatile("st.shared.b32 [%0], %1;"    :: "r"(a_st), "r"(h0) : "memory");
        asm volatile("st.shared.b32 [%0+16], %1;" :: "r"(a_st), "r"(h1) : "memory");
    }
    CP_WAIT(2);                                  // W_0 complete (thread-local)

    int komix = 1, c8mix = 0;                    // state for next mix = chunk 1

    for (int ci = 0; ci < NCHUNK; ci++) {
        __syncthreads();                          // publish A_ci + W_ci
        if (ci + 3 < NCHUNK) issue_chunk(sb + WBUF_OFF, ci + 3, tid);

        // fold conv accs before the first skip chunk's MMAs
        if (ci == NCHUNK_CONV) {
            const int cb = (lane & 3) * 2;
            #pragma unroll
            for (int g = 0; g < 8; g++) {
                float* a = acc + g * 4;
                int col = ncol + (g & 3) * 8 + cb;
                float2 bc  = *(const float2*)(s_bias + col);
                float2 bs2 = *(const float2*)(s_bias + 128 + col);
                a[0] = elu(a[0] + bc.x) + bs2.x;
                a[1] = elu(a[1] + bc.y) + bs2.y;
                a[2] = elu(a[2] + bc.x) + bs2.x;
                a[3] = elu(a[3] + bc.y) + bs2.y;
            }
        }

        // ---- MMA stream for chunk ci ----
        const uint32_t ab = a_l0 + (ci & 1) * BUF_B;
        const uint32_t wb = b_l0 + (ci & 3) * BUF_B;
        uint32_t a0[4], a1[4], bf0[4], bf1[4];
        ldsm_x4(a0, ab);
        ldsm_x4(a1, ab + 16 * ROW_SB);
        ldsm_x4(bf0, wb);
        ldsm_x4(bf1, wb + 16 * ROW_SB);

        // ---- mix stream for chunk ci+1 (independent; interleaves with MMA) ----
        const int mi = ci + 1;
        if (mi < NCHUNK_CONV) {
            if (komix == 0) {
                #pragma unroll
                for (int j = 0; j < KK; j++) {
                    float4 v = make_float4(0.f, 0.f, 0.f, 0.f);
                    if (noff[j] != 0xFFFFFFFFu)
                        v = __ldg((const float4*)((const char*)xb + (size_t)noff[j] + c8mix * 64 + q4));
                    xg[j] = v;
                }
            }
            const float* p = s_P2 + row * 108 + komix * 12;
            float4 pa = *(const float4*)p, pb = *(const float4*)(p + 4);
            float4 v = make_float4(0.f, 0.f, 0.f, 0.f);
            fma4(v, pa.x, xg[0]); fma4(v, pa.y, xg[1]);
            fma4(v, pa.z, xg[2]); fma4(v, pa.w, xg[3]);
            fma4(v, pb.x, xg[4]); fma4(v, pb.y, xg[5]);
            fma4(v, pb.z, xg[6]); fma4(v, pb.w, xg[7]);
            fma4(v, p[8], xg[8]);
            uint32_t h0 = h2pack(elu(v.x), elu(v.y));
            uint32_t h1 = h2pack(elu(v.z), elu(v.w));
            uint32_t ad = a_st + (mi & 1) * BUF_B;
            asm volatile("st.shared.b32 [%0], %1;"    :: "r"(ad), "r"(h0) : "memory");
            asm volatile("st.shared.b32 [%0+16], %1;" :: "r"(ad), "r"(h1) : "memory");
            if (++komix == 9) { komix = 0; c8mix++; }
        } else if (mi < NCHUNK) {
            int c8s = mi - NCHUNK_CONV;
            float4 v = __ldg((const float4*)((const char*)xb + (size_t)(n0 + row) * 512 + c8s * 64 + q4));
            uint32_t h0 = h2pack(v.x, v.y);
            uint32_t h1 = h2pack(v.z, v.w);
            uint32_t ad = a_st + (mi & 1) * BUF_B;
            asm volatile("st.shared.b32 [%0], %1;"    :: "r"(ad), "r"(h0) : "memory");
            asm volatile("st.shared.b32 [%0+16], %1;" :: "r"(ad), "r"(h1) : "memory");
        }

        // ---- MMAs (acc group g = (m-half, n-octet)) ----
        mma16816(acc + 0,  a0, bf0[0], bf0[2]);   // m0, n0-7
        mma16816(acc + 4,  a0, bf0[1], bf0[3]);   // m0, n8-15
        mma16816(acc + 8,  a0, bf1[0], bf1[2]);   // m0, n16-23
        mma16816(acc + 12, a0, bf1[1], bf1[3]);   // m0, n24-31
        mma16816(acc + 16, a1, bf0[0], bf0[2]);   // m16, n0-7
        mma16816(acc + 20, a1, bf0[1], bf0[3]);   // m16, n8-15
        mma16816(acc + 24, a1, bf1[0], bf1[2]);   // m16, n16-23
        mma16816(acc + 28, a1, bf1[1], bf1[3]);   // m16, n24-31

        // ensure W_(ci+1) complete (thread-local) before next barrier
        if (ci <= NCHUNK - 4)      { CP_WAIT(2); }
        else if (ci == NCHUNK - 3) { CP_WAIT(1); }
        else                       { CP_WAIT(0); }
    }

    // ---- epilogue: store (conv folded at ci==72; skip accumulated after) ----
    {
        const int cb = (lane & 3) * 2;
        #pragma unroll
        for (int g = 0; g < 8; g++) {
            float* a = acc + g * 4;
            int col = ncol + (g & 3) * 8 + cb;
            int mh  = (g >> 2) * 16;
            #pragma unroll
            for (int h = 0; h < 2; h++) {
                int r = mrow + mh + (lane >> 2) + h * 8;
                float* orow = out + ((size_t)b * NN + n0 + r) * CC;
                *(float2*)(orow + col) = make_float2(a[h * 2], a[h * 2 + 1]);
            }
        }
    }
}

extern "C" void kernel_launch(void* const* d_in, const int* in_sizes, int n_in,
                              void* d_out, int out_size) {
    const float* x       = (const float*)d_in[0];
    const int*   indices = (const int*)  d_in[1];
    const float* P       = (const float*)d_in[2];
    const float* W_conv  = (const float*)d_in[3];
    const float* b_conv  = (const float*)d_in[4];
    const float* W_skip  = (const float*)d_in[5];
    const float* b_skip  = (const float*)d_in[6];
    float* out = (float*)d_out;

    prep_w<<<(NCHUNK_CONV * 2048 + 255) / 256, 256>>>(W_conv, W_skip);

    cudaFuncSetAttribute(paiconv_pl,
                         cudaFuncAttributeMaxDynamicSharedMemorySize, SMEM_TOTAL);
    dim3 grid(NN / TM, BB);
    paiconv_pl<<<grid, THREADS, SMEM_TOTAL>>>(x, indices, P, b_conv, b_skip, out);
}

// round 12
// speedup vs baseline: 1.0956x; 1.0956x over previous
#include <cuda_runtime.h>
#include <cuda_fp16.h>
#include <cstdint>

#define BB 16
#define NN 16384
#define CC 128
#define KK 9
#define TM 64
#define THREADS 128
#define NCHUNK_CONV 72          // 8 c8-slices * 9 ko, K=16 each
#define NCHUNK 80               // + 8 skip chunks
#define NREG 40                 // 2 chunks per sync region
#define CHUNK_GB 4096
#define ROW_SB 48               // smem row stride: 32B data + 16B pad
#define BUF_B (128 * ROW_SB)    // 6144
#define NRING 6                 // W ring: 3 regions x 2 chunks

// smem layout (bytes), per CTA
#define WBUF_OFF 0                          // 6 * 6144 = 36864
#define P2_OFF   (NRING * BUF_B)            // 36864 (+ 64*108*4 = 27648)
#define IDX_OFF  (P2_OFF + TM * 108 * 4)    // 64512 (+ 64*9*4 = 2304)
#define BIAS_OFF (IDX_OFF + TM * KK * 4)    // 66816 (+ 1024)
#define SMEM_TOTAL (BIAS_OFF + 1024)        // 67840

// W pre-permuted fp16: [chunk][o(128)][p(16)]
__device__ __align__(16) __half g_Wc[NCHUNK_CONV * 2048];
__device__ __align__(16) __half g_Ws[8 * 2048];

// position p -> channel-within-16 (lane's 4 frag k-values = contiguous float4)
__host__ __device__ __forceinline__ int perm16(int p) {
    int e = p & 1;
    return (p < 8) ? ((p >> 1) * 4 + e) : (((p - 8) >> 1) * 4 + 2 + e);
}

__global__ void prep_w(const float* __restrict__ Wc, const float* __restrict__ Ws) {
    int t = blockIdx.x * blockDim.x + threadIdx.x;
    if (t < NCHUNK_CONV * 2048) {
        int q = t >> 11, r = t & 2047, o = r >> 4, p = r & 15;
        int c8 = q / 9, ko = q % 9;
        g_Wc[t] = __float2half_rn(Wc[o * 1152 + ko * CC + c8 * 16 + perm16(p)]);
    }
    if (t < 8 * 2048) {
        int q = t >> 11, r = t & 2047, o = r >> 4, p = r & 15;
        g_Ws[t] = __float2half_rn(Ws[o * CC + q * 16 + perm16(p)]);
    }
}

// ---------------- PTX helpers ----------------
__device__ __forceinline__ uint32_t smem_u32(const void* p) {
    uint32_t a;
    asm("{ .reg .u64 t; cvta.to.shared.u64 t, %1; cvt.u32.u64 %0, t; }" : "=r"(a) : "l"(p));
    return a;
}
#define CP_ASYNC16(dst, src) \
    asm volatile("cp.async.cg.shared.global [%0], [%1], 16;" :: "r"(dst), "l"(src))
#define CP_COMMIT() asm volatile("cp.async.commit_group;" ::: "memory")
#define CP_WAIT(n)  asm volatile("cp.async.wait_group %0;" :: "n"(n) : "memory")

__device__ __forceinline__ void ldsm_x4(uint32_t* r, uint32_t addr) {
    asm volatile("ldmatrix.sync.aligned.m8n8.x4.shared.b16 {%0,%1,%2,%3}, [%4];"
                 : "=r"(r[0]), "=r"(r[1]), "=r"(r[2]), "=r"(r[3]) : "r"(addr));
}
__device__ __forceinline__ void mma16816(float* c, const uint32_t* a,
                                         uint32_t b0, uint32_t b1) {
    asm volatile("mma.sync.aligned.m16n8k16.row.col.f32.f16.f16.f32 "
                 "{%0,%1,%2,%3}, {%4,%5,%6,%7}, {%8,%9}, {%0,%1,%2,%3};"
                 : "+f"(c[0]), "+f"(c[1]), "+f"(c[2]), "+f"(c[3])
                 : "r"(a[0]), "r"(a[1]), "r"(a[2]), "r"(a[3]), "r"(b0), "r"(b1));
}
__device__ __forceinline__ float elu(float v) {
    float e;
    asm("ex2.approx.f32 %0, %1;" : "=f"(e) : "f"(v * 1.44269504f));
    return v > 0.f ? v : e - 1.f;
}
__device__ __forceinline__ void fma4(float4& a, float s, const float4& v) {
    a.x = fmaf(s, v.x, a.x); a.y = fmaf(s, v.y, a.y);
    a.z = fmaf(s, v.z, a.z); a.w = fmaf(s, v.w, a.w);
}
__device__ __forceinline__ uint32_t h2pack(float a, float b) {
    __half2 h = __floats2half2_rn(a, b);
    return *reinterpret_cast<uint32_t*>(&h);
}

// region fetch: 2 chunks (8KB), 128 threads x 32B per chunk, ONE commit group
__device__ __forceinline__ void issue_region(uint32_t wbase, int r, int tid) {
    #pragma unroll
    for (int half = 0; half < 2; half++) {
        int ci = 2 * r + half;
        const char* src0 = (ci < NCHUNK_CONV)
            ? (const char*)g_Wc + (size_t)ci * CHUNK_GB
            : (const char*)g_Ws + (size_t)(ci - NCHUNK_CONV) * CHUNK_GB;
        uint32_t dbase = wbase + (ci % NRING) * BUF_B;
        #pragma unroll
        for (int e = 0; e < 2; e++) {
            int id = tid + e * THREADS;           // 0..255
            int o = id >> 1, h = id & 1;
            CP_ASYNC16(dbase + o * ROW_SB + h * 16, src0 + o * 32 + h * 16);
        }
    }
    CP_COMMIT();
}

__global__ __launch_bounds__(THREADS, 2)
void paiconv_2c(const float* __restrict__ x, const int* __restrict__ idxg,
                const float* __restrict__ P, const float* __restrict__ b_conv,
                const float* __restrict__ b_skip, float* __restrict__ out)
{
    extern __shared__ char smem[];
    const uint32_t sb = smem_u32(smem);
    const int tid  = threadIdx.x;
    const int lane = tid & 31;
    const int wid  = tid >> 5;                   // 0..3
    const int n0   = blockIdx.x * TM;
    const int b    = blockIdx.y;

    float* s_P2   = (float*)(smem + P2_OFF);     // [node][ko][12]
    int*   s_idx  = (int*)(smem + IDX_OFF);
    float* s_bias = (float*)(smem + BIAS_OFF);

    // start W pipeline: regions 0,1 (chunks 0..3)
    issue_region(sb + WBUF_OFF, 0, tid);
    issue_region(sb + WBUF_OFF, 1, tid);

    for (int t = tid; t < TM * 81; t += THREADS) {
        int node = t / 81, rem = t - node * 81;
        int ko = rem / 9, j = rem - ko * 9;
        s_P2[node * 108 + ko * 12 + j] = P[(size_t)n0 * 81 + t];
    }
    for (int t = tid; t < TM * KK; t += THREADS) s_idx[t] = idxg[n0 * KK + t];
    if (tid < CC) { s_bias[tid] = b_conv[tid]; s_bias[CC + tid] = b_skip[tid]; }
    __syncthreads();

    const float* xb = x + (size_t)b * NN * CC;

    // lane-owned rows within warp m16 tile (4 warps cover 64 nodes)
    const int r0l = wid * 16 + (lane >> 2);
    const int r1l = r0l + 8;
    const int q4  = (lane & 3) * 16;             // byte offset of lane's float4

    int idxr[2][KK];
    #pragma unroll
    for (int j = 0; j < KK; j++) {
        idxr[0][j] = s_idx[r0l * KK + j];
        idxr[1][j] = s_idx[r1l * KK + j];
    }

    float acc[64];
    #pragma unroll
    for (int i = 0; i < 64; i++) acc[i] = 0.f;

    float4 xg[2][KK];
    const uint32_t ldsm_base = sb + WBUF_OFF + (lane & 15) * ROW_SB + (lane >> 4) * 16;

    int ci = 0, komix = 0, c8mix = 0;
    for (int r = 0; r < NREG; r++) {
        if (r < NREG - 2) { CP_WAIT(1); } else { CP_WAIT(0); }
        __syncthreads();
        if (r + 2 < NREG) issue_region(sb + WBUF_OFF, r + 2, tid);

        #pragma unroll
        for (int half = 0; half < 2; half++, ci++) {
            uint32_t a[4];
            if (ci < NCHUNK_CONV) {
                if (komix == 0) {
                    // gather c8 slice for 2 rows x 9 neighbors (fp32, reused 9x)
                    #pragma unroll
                    for (int rr = 0; rr < 2; rr++)
                        #pragma unroll
                        for (int j = 0; j < KK; j++) {
                            int ix = idxr[rr][j];
                            float4 v = make_float4(0.f, 0.f, 0.f, 0.f);
                            if ((unsigned)ix < (unsigned)NN)
                                v = __ldg((const float4*)((const char*)xb + (size_t)ix * 512 + c8mix * 64 + q4));
                            xg[rr][j] = v;
                        }
                }
                const float* p0 = s_P2 + r0l * 108 + komix * 12;
                const float* p1 = s_P2 + r1l * 108 + komix * 12;
                float4 pa0 = *(const float4*)p0, pb0 = *(const float4*)(p0 + 4);
                float4 pa1 = *(const float4*)p1, pb1 = *(const float4*)(p1 + 4);
                float4 v0 = make_float4(0.f, 0.f, 0.f, 0.f);
                float4 v1 = make_float4(0.f, 0.f, 0.f, 0.f);
                fma4(v0, pa0.x, xg[0][0]); fma4(v1, pa1.x, xg[1][0]);
                fma4(v0, pa0.y, xg[0][1]); fma4(v1, pa1.y, xg[1][1]);
                fma4(v0, pa0.z, xg[0][2]); fma4(v1, pa1.z, xg[1][2]);
                fma4(v0, pa0.w, xg[0][3]); fma4(v1, pa1.w, xg[1][3]);
                fma4(v0, pb0.x, xg[0][4]); fma4(v1, pb1.x, xg[1][4]);
                fma4(v0, pb0.y, xg[0][5]); fma4(v1, pb1.y, xg[1][5]);
                fma4(v0, pb0.z, xg[0][6]); fma4(v1, pb1.z, xg[1][6]);
                fma4(v0, pb0.w, xg[0][7]); fma4(v1, pb1.w, xg[1][7]);
                fma4(v0, p0[8], xg[0][8]); fma4(v1, p1[8], xg[1][8]);

                a[0] = h2pack(elu(v0.x), elu(v0.y));
                a[1] = h2pack(elu(v1.x), elu(v1.y));
                a[2] = h2pack(elu(v0.z), elu(v0.w));
                a[3] = h2pack(elu(v1.z), elu(v1.w));
                if (++komix == 9) { komix = 0; c8mix++; }
            } else {
                // fold conv accs once, before first skip chunk's MMAs
                if (ci == NCHUNK_CONV) {
                    const int cbase = (lane & 3) * 2;
                    #pragma unroll
                    for (int t = 0; t < 16; t++) {
                        int col = t * 8 + cbase;
                        float2 bc  = *(const float2*)(s_bias + col);
                        float2 bs2 = *(const float2*)(s_bias + 128 + col);
                        acc[t * 4 + 0] = elu(acc[t * 4 + 0] + bc.x) + bs2.x;
                        acc[t * 4 + 1] = elu(acc[t * 4 + 1] + bc.y) + bs2.y;
                        acc[t * 4 + 2] = elu(acc[t * 4 + 2] + bc.x) + bs2.x;
                        acc[t * 4 + 3] = elu(acc[t * 4 + 3] + bc.y) + bs2.y;
                    }
                }
                int c8s = ci - NCHUNK_CONV;
                float4 v0 = __ldg((const float4*)((const char*)xb + (size_t)(n0 + r0l) * 512 + c8s * 64 + q4));
                float4 v1 = __ldg((const float4*)((const char*)xb + (size_t)(n0 + r1l) * 512 + c8s * 64 + q4));
                a[0] = h2pack(v0.x, v0.y);
                a[1] = h2pack(v1.x, v1.y);
                a[2] = h2pack(v0.z, v0.w);
                a[3] = h2pack(v1.z, v1.w);
            }

            const uint32_t wb = ldsm_base + (ci % NRING) * BUF_B;
            #pragma unroll
            for (int g = 0; g < 8; g++) {
                uint32_t bf[4];
                ldsm_x4(bf, wb + g * 16 * ROW_SB);
                mma16816(acc + (2 * g) * 4,     a, bf[0], bf[2]);
                mma16816(acc + (2 * g + 1) * 4, a, bf[1], bf[3]);
            }
        }
    }

    // ---------------- epilogue: store ----------------
    {
        const int cbase = (lane & 3) * 2;
        float* o0 = out + ((size_t)b * NN + n0 + r0l) * CC + cbase;
        float* o1 = out + ((size_t)b * NN + n0 + r1l) * CC + cbase;
        #pragma unroll
        for (int t = 0; t < 16; t++) {
            *(float2*)(o0 + t * 8) = make_float2(acc[t * 4 + 0], acc[t * 4 + 1]);
            *(float2*)(o1 + t * 8) = make_float2(acc[t * 4 + 2], acc[t * 4 + 3]);
        }
    }
}

extern "C" void kernel_launch(void* const* d_in, const int* in_sizes, int n_in,
                              void* d_out, int out_size) {
    const float* x       = (const float*)d_in[0];
    const int*   indices = (const int*)  d_in[1];
    const float* P       = (const float*)d_in[2];
    const float* W_conv  = (const float*)d_in[3];
    const float* b_conv  = (const float*)d_in[4];
    const float* W_skip  = (const float*)d_in[5];
    const float* b_skip  = (const float*)d_in[6];
    float* out = (float*)d_out;

    prep_w<<<(NCHUNK_CONV * 2048 + 255) / 256, 256>>>(W_conv, W_skip);

    cudaFuncSetAttribute(paiconv_2c,
                         cudaFuncAttributeMaxDynamicSharedMemorySize, SMEM_TOTAL);
    dim3 grid(NN / TM, BB);
    paiconv_2c<<<grid, THREADS, SMEM_TOTAL>>>(x, indices, P, b_conv, b_skip, out);
}